// round 15
// baseline (speedup 1.0000x reference)
#include <cuda_runtime.h>
#include <cuda_fp16.h>

#define BB 8
#define LL 1000
#define DD 1024
#define HH 16
#define HDIM 64
#define MTOT (BB * LL)   // 8000

// Scratch (__device__ globals; allocation-free rule)
__device__ __align__(16) __half g_xh[(size_t)MTOT * DD];
__device__ __align__(16) __half g_wqkvh[(size_t)DD * 3 * DD];
__device__ __align__(16) __half g_woh[(size_t)DD * DD];
__device__ __align__(16) __half g_qkvh[(size_t)MTOT * 3 * DD];
__device__ __align__(16) __half g_atth[(size_t)MTOT * DD];

// ---------------------------------------------------------------------------
// helpers
// ---------------------------------------------------------------------------
__device__ __forceinline__ void mma_f16(float* c, const unsigned* a, const unsigned* b) {
    asm volatile(
        "mma.sync.aligned.m16n8k16.row.col.f32.f16.f16.f32 "
        "{%0,%1,%2,%3},{%4,%5,%6,%7},{%8,%9},{%0,%1,%2,%3};"
        : "+f"(c[0]), "+f"(c[1]), "+f"(c[2]), "+f"(c[3])
        : "r"(a[0]), "r"(a[1]), "r"(a[2]), "r"(a[3]), "r"(b[0]), "r"(b[1]));
}

__device__ __forceinline__ void ldsm_x4(unsigned& r0, unsigned& r1,
                                        unsigned& r2, unsigned& r3, const void* p) {
    unsigned addr = (unsigned)__cvta_generic_to_shared(p);
    asm volatile("ldmatrix.sync.aligned.m8n8.x4.shared.b16 {%0,%1,%2,%3}, [%4];"
                 : "=r"(r0), "=r"(r1), "=r"(r2), "=r"(r3) : "r"(addr));
}
__device__ __forceinline__ void ldsm_x4_t(unsigned& r0, unsigned& r1,
                                          unsigned& r2, unsigned& r3, const void* p) {
    unsigned addr = (unsigned)__cvta_generic_to_shared(p);
    asm volatile("ldmatrix.sync.aligned.m8n8.x4.trans.shared.b16 {%0,%1,%2,%3}, [%4];"
                 : "=r"(r0), "=r"(r1), "=r"(r2), "=r"(r3) : "r"(addr));
}
__device__ __forceinline__ void ldsm_x2_t(unsigned& r0, unsigned& r1, const void* p) {
    unsigned addr = (unsigned)__cvta_generic_to_shared(p);
    asm volatile("ldmatrix.sync.aligned.m8n8.x2.trans.shared.b16 {%0,%1}, [%2];"
                 : "=r"(r0), "=r"(r1) : "r"(addr));
}

__device__ __forceinline__ void cp_async16(void* smem_dst, const void* gsrc, bool pred) {
    unsigned saddr = (unsigned)__cvta_generic_to_shared(smem_dst);
    int sz = pred ? 16 : 0;
    asm volatile("cp.async.cg.shared.global [%0], [%1], 16, %2;\n"
                 :: "r"(saddr), "l"(gsrc), "r"(sz));
}
__device__ __forceinline__ void cp_commit() { asm volatile("cp.async.commit_group;\n" ::); }
template <int N>
__device__ __forceinline__ void cp_wait() { asm volatile("cp.async.wait_group %0;\n" :: "n"(N)); }

__device__ __forceinline__ unsigned h2u(__half2 h) { return *(unsigned*)&h; }
__device__ __forceinline__ __half2 u2h(unsigned u) { return *(__half2*)&u; }

// two fp16 exp2 in one MUFU op
__device__ __forceinline__ unsigned ex2_f16x2(unsigned x) {
    unsigned d;
    asm("ex2.approx.f16x2 %0, %1;" : "=r"(d) : "r"(x));
    return d;
}

// ---------------------------------------------------------------------------
// merged fp32 -> fp16 conversion for x, Wqkv, Wo (one launch)
// ---------------------------------------------------------------------------
#define CN1 (MTOT * DD)
#define CN2 (3 * DD * DD)
#define CN3 (DD * DD)
__global__ void convert_all_kernel(const float* __restrict__ x,
                                   const float* __restrict__ wqkv,
                                   const float* __restrict__ wo,
                                   __half* __restrict__ xh,
                                   __half* __restrict__ wqkvh,
                                   __half* __restrict__ woh)
{
    int i = (blockIdx.x * blockDim.x + threadIdx.x) * 4;
    const float* src;
    __half* dst;
    int off;
    if (i < CN1)             { src = x;    dst = xh;    off = i; }
    else if (i < CN1 + CN2)  { src = wqkv; dst = wqkvh; off = i - CN1; }
    else if (i < CN1 + CN2 + CN3) { src = wo; dst = woh; off = i - CN1 - CN2; }
    else return;
    float4 v = *(const float4*)(src + off);
    *(__half2*)(dst + off)     = __floats2half2_rn(v.x, v.y);
    *(__half2*)(dst + off + 2) = __floats2half2_rn(v.z, v.w);
}

// ---------------------------------------------------------------------------
// FP16 tensor-core GEMM: C = A*B + bias.
// Block tile 128x128x32, 128 thr = 4 warps, warp tile 64x64.
// 4-stage cp.async pipeline; exactly one commit per iteration.
// B fragments software-pipelined one n-group ahead to hide LDSM latency.
// ---------------------------------------------------------------------------
#define TBM 128
#define TBN 128
#define TBK 32
#define ASTR 40
#define BSTR 136
#define ASZH (TBM * ASTR)
#define BSZH (TBK * BSTR)
#define SSZ  (ASZH + BSZH)
#define NSTAGE 4
#define GEMM_SMEM_BYTES (NSTAGE * SSZ * 2)   // 75776

__device__ __forceinline__ void gemm_issue_tile(
    __half* As, const __half* __restrict__ A, const __half* __restrict__ Bm,
    int bm, int bn, int M, int N, int K, int t, int stage, int tid)
{
    __half* Ad = As + stage * SSZ;
    __half* Bd = Ad + ASZH;
    int k0 = t * TBK;
    #pragma unroll
    for (int i = 0; i < 4; i++) {
        int chunk = tid + i * 128;
        int row = chunk >> 2, c8 = (chunk & 3) * 8;
        bool ok = (bm + row) < M;
        cp_async16(Ad + row * ASTR + c8, A + (size_t)(bm + row) * K + k0 + c8, ok);
    }
    #pragma unroll
    for (int i = 0; i < 4; i++) {
        int chunk = tid + i * 128;
        int row = chunk >> 4, c8 = (chunk & 15) * 8;
        cp_async16(Bd + row * BSTR + c8, Bm + (size_t)(k0 + row) * N + bn + c8, true);
    }
    cp_commit();
}

template <bool OUT_HALF>
__global__ __launch_bounds__(128, 2) void gemm_f16_kernel(
    const __half* __restrict__ A, const __half* __restrict__ Bm,
    const float* __restrict__ bias, void* __restrict__ Cout,
    int M, int N, int K)
{
    extern __shared__ __align__(16) char smem_raw[];
    __half* As = (__half*)smem_raw;

    const int tid = threadIdx.x;
    const int lane = tid & 31;
    const int warp = tid >> 5;
    const int wm = (warp & 1) * 64;
    const int wn = (warp >> 1) * 64;
    const int bm = blockIdx.y * TBM;
    const int bn = blockIdx.x * TBN;

    // prefetch bias for this thread's 8 n-tiles (hidden under the k-loop)
    float bpre[8][2];
    #pragma unroll
    for (int nt = 0; nt < 8; nt++) {
        int col = bn + wn + nt * 8 + (lane & 3) * 2;
        bpre[nt][0] = bias[col];
        bpre[nt][1] = bias[col + 1];
    }

    float acc[4][8][4];
    #pragma unroll
    for (int i = 0; i < 4; i++)
        #pragma unroll
        for (int j = 0; j < 8; j++)
            #pragma unroll
            for (int r = 0; r < 4; r++) acc[i][j][r] = 0.f;

    const int nT = K / TBK;

    gemm_issue_tile(As, A, Bm, bm, bn, M, N, K, 0, 0, tid);
    gemm_issue_tile(As, A, Bm, bm, bn, M, N, K, 1, 1, tid);
    gemm_issue_tile(As, A, Bm, bm, bn, M, N, K, 2, 2, tid);

    int stage = 0;
    for (int t = 0; t < nT; t++) {
        cp_wait<2>();
        __syncthreads();

        if (t + 3 < nT)
            gemm_issue_tile(As, A, Bm, bm, bn, M, N, K,
                            t + 3, (stage + 3) % NSTAGE, tid);
        else
            cp_commit();     // keep the exactly-one-commit-per-iter invariant

        const __half* Ab = As + stage * SSZ;
        const __half* Bb = Ab + ASZH;

        #pragma unroll
        for (int ks = 0; ks < 2; ks++) {
            int k = ks * 16;
            unsigned afr[4][4];
            #pragma unroll
            for (int mt = 0; mt < 4; mt++) {
                const __half* p = Ab + (size_t)(wm + mt * 16 + (lane & 15)) * ASTR
                                  + k + ((lane >> 4) << 3);
                ldsm_x4(afr[mt][0], afr[mt][1], afr[mt][2], afr[mt][3], p);
            }
            // B fragments pipelined one np ahead: LDSM latency hides under MMAs
            unsigned bc[4];
            {
                const __half* p = Bb + (size_t)(k + (lane & 15)) * BSTR
                                  + wn + ((lane >> 4) << 3);
                ldsm_x4_t(bc[0], bc[1], bc[2], bc[3], p);
            }
            #pragma unroll
            for (int np = 0; np < 4; np++) {
                unsigned bnx[4];
                if (np < 3) {
                    const __half* p = Bb + (size_t)(k + (lane & 15)) * BSTR
                                      + wn + (np + 1) * 16 + ((lane >> 4) << 3);
                    ldsm_x4_t(bnx[0], bnx[1], bnx[2], bnx[3], p);
                }
                #pragma unroll
                for (int mt = 0; mt < 4; mt++) {
                    mma_f16(acc[mt][2 * np],     afr[mt], bc);
                    mma_f16(acc[mt][2 * np + 1], afr[mt], bc + 2);
                }
                if (np < 3) {
                    bc[0] = bnx[0]; bc[1] = bnx[1];
                    bc[2] = bnx[2]; bc[3] = bnx[3];
                }
            }
        }
        stage = (stage + 1) % NSTAGE;
    }

    #pragma unroll
    for (int mt = 0; mt < 4; mt++) {
        int r_lo = bm + wm + mt * 16 + (lane >> 2);
        int r_hi = r_lo + 8;
        #pragma unroll
        for (int nt = 0; nt < 8; nt++) {
            int col = bn + wn + nt * 8 + (lane & 3) * 2;
            float b0 = bpre[nt][0], b1 = bpre[nt][1];
            if (OUT_HALF) {
                __half* C = (__half*)Cout;
                if (r_lo < M)
                    *(__half2*)(C + (size_t)r_lo * N + col) =
                        __floats2half2_rn(acc[mt][nt][0] + b0, acc[mt][nt][1] + b1);
                if (r_hi < M)
                    *(__half2*)(C + (size_t)r_hi * N + col) =
                        __floats2half2_rn(acc[mt][nt][2] + b0, acc[mt][nt][3] + b1);
            } else {
                float* C = (float*)Cout;
                if (r_lo < M)
                    *(float2*)(C + (size_t)r_lo * N + col) =
                        make_float2(acc[mt][nt][0] + b0, acc[mt][nt][1] + b1);
                if (r_hi < M)
                    *(float2*)(C + (size_t)r_hi * N + col) =
                        make_float2(acc[mt][nt][2] + b0, acc[mt][nt][3] + b1);
            }
        }
    }
}

// ---------------------------------------------------------------------------
// FP16 flash attention (causal). 128 thr = 4 warps; Q tile 64 rows.
// log2-space softmax; fp16x2 MUFU exp; row-sum via ones-column in V padding;
// 3 CTAs/SM. Diagonal step skips fully-masked S n-tiles (np > warp).
// ---------------------------------------------------------------------------
#define QSTR 72
#define AT_TILEH (64 * QSTR)
#define ATTN_SMEM_BYTES (5 * AT_TILEH * 2)   // 46080

__device__ __forceinline__ void attn_issue_kv(
    __half* kdst, __half* vdst, const __half* kptr, const __half* vptr,
    int j, int tid)
{
    #pragma unroll
    for (int i = 0; i < 4; i++) {
        int chunk = tid + i * 128;
        int r = chunk >> 3;
        int c = (chunk & 7) * 8;
        int kv = j * 64 + r;
        if (kv >= LL) kv = LL - 1;   // clamped; masked in S
        cp_async16(kdst + r * QSTR + c, kptr + (size_t)kv * (3 * DD) + c, true);
        cp_async16(vdst + r * QSTR + c, vptr + (size_t)kv * (3 * DD) + c, true);
    }
}

__global__ __launch_bounds__(128, 3) void attn_f16_kernel(
    const __half* __restrict__ qkv, __half* __restrict__ att)
{
    extern __shared__ __align__(16) char smem_raw[];
    __half* qs = (__half*)smem_raw;
    __half* ks = qs + AT_TILEH;
    __half* vs = ks + 2 * AT_TILEH;

    const int tid = threadIdx.x;
    const int lane = tid & 31;
    const int warp = tid >> 5;
    const int qtile = 15 - blockIdx.x;
    const int bh = blockIdx.y;
    const int b = bh >> 4;
    const int h = bh & 15;
    const int q0 = qtile * 64;

    const size_t base = (size_t)b * LL * (3 * DD);
    const __half* qptr = qkv + base + h * HDIM;
    const __half* kptr = qkv + base + DD + h * HDIM;
    const __half* vptr = qkv + base + 2 * DD + h * HDIM;

    attn_issue_kv(ks, vs, kptr, vptr, 0, tid);
    #pragma unroll
    for (int i = 0; i < 4; i++) {
        int chunk = tid + i * 128;
        int r = chunk >> 3;
        int c = (chunk & 7) * 8;
        int qr = q0 + r;
        if (qr >= LL) qr = LL - 1;
        cp_async16(qs + r * QSTR + c, qptr + (size_t)qr * (3 * DD) + c, true);
    }
    cp_commit();

    // Ones in V padding cols 64..71 (both buffers) -> PV extra n-tile = row sums.
    {
        const unsigned ONE2 = 0x3C003C00u;
        uint4 ones4 = make_uint4(ONE2, ONE2, ONE2, ONE2);
        int buf = tid >> 6, row = tid & 63;
        *(uint4*)(vs + buf * AT_TILEH + row * QSTR + 64) = ones4;
    }
    cp_wait<0>();
    __syncthreads();

    // Q fragments, pre-scaled by 0.125 * log2(e)
    const __half2 sc2 = __float2half2_rn(0.125f * 1.4426950408889634f);
    unsigned qa[4][4];
    #pragma unroll
    for (int kc = 0; kc < 4; kc++) {
        const __half* p = qs + (size_t)(warp * 16 + (lane & 15)) * QSTR
                          + kc * 16 + ((lane >> 4) << 3);
        ldsm_x4(qa[kc][0], qa[kc][1], qa[kc][2], qa[kc][3], p);
        #pragma unroll
        for (int i = 0; i < 4; i++)
            qa[kc][i] = h2u(__hmul2(u2h(qa[kc][i]), sc2));
    }

    float o[8][4];
    #pragma unroll
    for (int nt = 0; nt < 8; nt++)
        #pragma unroll
        for (int r = 0; r < 4; r++) o[nt][r] = 0.f;
    float ol[4] = {0.f, 0.f, 0.f, 0.f};
    float m0 = -1e30f, m1 = -1e30f;

    for (int j = 0; j <= qtile; j++) {
        int cur = j & 1;
        int nxt = cur ^ 1;
        if (j > 0) { cp_wait<0>(); __syncthreads(); }

        if (j < qtile) {
            attn_issue_kv(ks + nxt * AT_TILEH, vs + nxt * AT_TILEH,
                          kptr, vptr, j + 1, tid);
            cp_commit();
        }

        const __half* K = ks + cur * AT_TILEH;
        const __half* V = vs + cur * AT_TILEH;

        float s[8][4];
        #pragma unroll
        for (int nt = 0; nt < 8; nt++)
            #pragma unroll
            for (int r = 0; r < 4; r++) s[nt][r] = 0.f;

        if (j < qtile) {
            #pragma unroll
            for (int kc = 0; kc < 4; kc++) {
                #pragma unroll
                for (int np = 0; np < 4; np++) {
                    unsigned b0[2], b1[2];
                    const __half* p = K + (size_t)(np * 16 + (lane & 7) + ((lane >> 1) & 8)) * QSTR
                                      + kc * 16 + (lane & 8);
                    ldsm_x4(b0[0], b0[1], b1[0], b1[1], p);
                    mma_f16(s[2 * np],     qa[kc], b0);
                    mma_f16(s[2 * np + 1], qa[kc], b1);
                }
            }
        } else {
            // diagonal step: n-tiles with np > warp are fully masked -> skip
            #pragma unroll
            for (int kc = 0; kc < 4; kc++) {
                #pragma unroll
                for (int np = 0; np < 4; np++) {
                    if (np <= warp) {
                        unsigned b0[2], b1[2];
                        const __half* p = K + (size_t)(np * 16 + (lane & 7) + ((lane >> 1) & 8)) * QSTR
                                          + kc * 16 + (lane & 8);
                        ldsm_x4(b0[0], b0[1], b1[0], b1[1], p);
                        mma_f16(s[2 * np],     qa[kc], b0);
                        mma_f16(s[2 * np + 1], qa[kc], b1);
                    }
                }
            }
        }

        if (j == qtile) {
            int row_g0 = q0 + warp * 16 + (lane >> 2);
            int row_g1 = row_g0 + 8;
            #pragma unroll
            for (int nt = 0; nt < 8; nt++) {
                int c0 = q0 + nt * 8 + 2 * (lane & 3);
                int c1 = c0 + 1;
                if (c0 > row_g0 || c0 >= LL) s[nt][0] = -1e30f;
                if (c1 > row_g0 || c1 >= LL) s[nt][1] = -1e30f;
                if (c0 > row_g1 || c0 >= LL) s[nt][2] = -1e30f;
                if (c1 > row_g1 || c1 >= LL) s[nt][3] = -1e30f;
            }
        }

        float mx0 = m0, mx1 = m1;
        #pragma unroll
        for (int nt = 0; nt < 8; nt++) {
            mx0 = fmaxf(mx0, fmaxf(s[nt][0], s[nt][1]));
            mx1 = fmaxf(mx1, fmaxf(s[nt][2], s[nt][3]));
        }
        mx0 = fmaxf(mx0, __shfl_xor_sync(0xffffffff, mx0, 1));
        mx0 = fmaxf(mx0, __shfl_xor_sync(0xffffffff, mx0, 2));
        mx1 = fmaxf(mx1, __shfl_xor_sync(0xffffffff, mx1, 1));
        mx1 = fmaxf(mx1, __shfl_xor_sync(0xffffffff, mx1, 2));

        float a0 = exp2f(m0 - mx0);
        float a1 = exp2f(m1 - mx1);
        m0 = mx0; m1 = mx1;

        unsigned pa[4][4];
        #pragma unroll
        for (int kc = 0; kc < 4; kc++) {
            pa[kc][0] = ex2_f16x2(h2u(__floats2half2_rn(s[2 * kc][0] - mx0,
                                                        s[2 * kc][1] - mx0)));
            pa[kc][1] = ex2_f16x2(h2u(__floats2half2_rn(s[2 * kc][2] - mx1,
                                                        s[2 * kc][3] - mx1)));
            pa[kc][2] = ex2_f16x2(h2u(__floats2half2_rn(s[2 * kc + 1][0] - mx0,
                                                        s[2 * kc + 1][1] - mx0)));
            pa[kc][3] = ex2_f16x2(h2u(__floats2half2_rn(s[2 * kc + 1][2] - mx1,
                                                        s[2 * kc + 1][3] - mx1)));
        }

        #pragma unroll
        for (int nt = 0; nt < 8; nt++) {
            o[nt][0] *= a0; o[nt][1] *= a0;
            o[nt][2] *= a1; o[nt][3] *= a1;
        }
        ol[0] *= a0; ol[1] *= a0; ol[2] *= a1; ol[3] *= a1;

        #pragma unroll
        for (int kc = 0; kc < 4; kc++) {
            #pragma unroll
            for (int np = 0; np < 4; np++) {
                unsigned b0[2], b1[2];
                const __half* p = V + (size_t)(kc * 16 + (lane & 15)) * QSTR
                                  + np * 16 + ((lane >> 4) << 3);
                ldsm_x4_t(b0[0], b0[1], b1[0], b1[1], p);
                mma_f16(o[2 * np],     pa[kc], b0);
                mma_f16(o[2 * np + 1], pa[kc], b1);
            }
            unsigned bl[2];
            ldsm_x2_t(bl[0], bl[1],
                      V + (size_t)(kc * 16 + (lane & 15)) * QSTR + 64);
            mma_f16(ol, pa[kc], bl);
        }
    }

    float inv0 = 1.0f / ol[0];
    float inv1 = 1.0f / ol[2];
    int row0 = q0 + warp * 16 + (lane >> 2);
    int row1 = row0 + 8;
    #pragma unroll
    for (int nt = 0; nt < 8; nt++) {
        int col = h * HDIM + nt * 8 + 2 * (lane & 3);
        if (row0 < LL)
            *(__half2*)(att + (size_t)(b * LL + row0) * DD + col) =
                __floats2half2_rn(o[nt][0] * inv0, o[nt][1] * inv0);
        if (row1 < LL)
            *(__half2*)(att + (size_t)(b * LL + row1) * DD + col) =
                __floats2half2_rn(o[nt][2] * inv1, o[nt][3] * inv1);
    }
}

// ---------------------------------------------------------------------------
extern "C" void kernel_launch(void* const* d_in, const int* in_sizes, int n_in,
                              void* d_out, int out_size)
{
    const float* x    = (const float*)d_in[0];
    const float* Wqkv = (const float*)d_in[1];
    const float* bqkv = (const float*)d_in[2];
    const float* Wo   = (const float*)d_in[3];
    const float* bo   = (const float*)d_in[4];
    float* out = (float*)d_out;

    __half *xh, *wqkvh, *woh, *qkvh, *atth;
    cudaGetSymbolAddress((void**)&xh, g_xh);
    cudaGetSymbolAddress((void**)&wqkvh, g_wqkvh);
    cudaGetSymbolAddress((void**)&woh, g_woh);
    cudaGetSymbolAddress((void**)&qkvh, g_qkvh);
    cudaGetSymbolAddress((void**)&atth, g_atth);

    cudaFuncSetAttribute(gemm_f16_kernel<true>,
                         cudaFuncAttributeMaxDynamicSharedMemorySize, GEMM_SMEM_BYTES);
    cudaFuncSetAttribute(gemm_f16_kernel<false>,
                         cudaFuncAttributeMaxDynamicSharedMemorySize, GEMM_SMEM_BYTES);
    cudaFuncSetAttribute(attn_f16_kernel,
                         cudaFuncAttributeMaxDynamicSharedMemorySize, ATTN_SMEM_BYTES);

    // 0) all fp32->fp16 conversions in one launch
    {
        int total4 = (CN1 + CN2 + CN3) / 4;
        convert_all_kernel<<<(total4 + 255) / 256, 256>>>(x, Wqkv, Wo, xh, wqkvh, woh);
    }

    const int gridM = (MTOT + TBM - 1) / TBM;  // 63

    gemm_f16_kernel<true><<<dim3(3 * DD / TBN, gridM), 128, GEMM_SMEM_BYTES>>>(
        xh, wqkvh, bqkv, qkvh, MTOT, 3 * DD, DD);

    attn_f16_kernel<<<dim3(16, BB * HH), 128, ATTN_SMEM_BYTES>>>(qkvh, atth);

    gemm_f16_kernel<false><<<dim3(DD / TBN, gridM), 128, GEMM_SMEM_BYTES>>>(
        atth, woh, bo, out, MTOT, DD, DD);
}

// round 16
// speedup vs baseline: 1.0173x; 1.0173x over previous
#include <cuda_runtime.h>
#include <cuda_fp16.h>

#define BB 8
#define LL 1000
#define DD 1024
#define HH 16
#define HDIM 64
#define MTOT (BB * LL)   // 8000

// Scratch (__device__ globals; allocation-free rule)
__device__ __align__(16) __half g_xh[(size_t)MTOT * DD];
__device__ __align__(16) __half g_wqkvh[(size_t)DD * 3 * DD];
__device__ __align__(16) __half g_woh[(size_t)DD * DD];
__device__ __align__(16) __half g_qkvh[(size_t)MTOT * 3 * DD];
__device__ __align__(16) __half g_atth[(size_t)MTOT * DD];

// ---------------------------------------------------------------------------
// helpers
// ---------------------------------------------------------------------------
__device__ __forceinline__ void mma_f16(float* c, const unsigned* a, const unsigned* b) {
    asm volatile(
        "mma.sync.aligned.m16n8k16.row.col.f32.f16.f16.f32 "
        "{%0,%1,%2,%3},{%4,%5,%6,%7},{%8,%9},{%0,%1,%2,%3};"
        : "+f"(c[0]), "+f"(c[1]), "+f"(c[2]), "+f"(c[3])
        : "r"(a[0]), "r"(a[1]), "r"(a[2]), "r"(a[3]), "r"(b[0]), "r"(b[1]));
}

__device__ __forceinline__ void ldsm_x4(unsigned& r0, unsigned& r1,
                                        unsigned& r2, unsigned& r3, const void* p) {
    unsigned addr = (unsigned)__cvta_generic_to_shared(p);
    asm volatile("ldmatrix.sync.aligned.m8n8.x4.shared.b16 {%0,%1,%2,%3}, [%4];"
                 : "=r"(r0), "=r"(r1), "=r"(r2), "=r"(r3) : "r"(addr));
}
__device__ __forceinline__ void ldsm_x4_t(unsigned& r0, unsigned& r1,
                                          unsigned& r2, unsigned& r3, const void* p) {
    unsigned addr = (unsigned)__cvta_generic_to_shared(p);
    asm volatile("ldmatrix.sync.aligned.m8n8.x4.trans.shared.b16 {%0,%1,%2,%3}, [%4];"
                 : "=r"(r0), "=r"(r1), "=r"(r2), "=r"(r3) : "r"(addr));
}
__device__ __forceinline__ void ldsm_x2_t(unsigned& r0, unsigned& r1, const void* p) {
    unsigned addr = (unsigned)__cvta_generic_to_shared(p);
    asm volatile("ldmatrix.sync.aligned.m8n8.x2.trans.shared.b16 {%0,%1}, [%2];"
                 : "=r"(r0), "=r"(r1) : "r"(addr));
}

__device__ __forceinline__ void cp_async16(void* smem_dst, const void* gsrc, bool pred) {
    unsigned saddr = (unsigned)__cvta_generic_to_shared(smem_dst);
    int sz = pred ? 16 : 0;
    asm volatile("cp.async.cg.shared.global [%0], [%1], 16, %2;\n"
                 :: "r"(saddr), "l"(gsrc), "r"(sz));
}
__device__ __forceinline__ void cp_commit() { asm volatile("cp.async.commit_group;\n" ::); }
template <int N>
__device__ __forceinline__ void cp_wait() { asm volatile("cp.async.wait_group %0;\n" :: "n"(N)); }

__device__ __forceinline__ unsigned h2u(__half2 h) { return *(unsigned*)&h; }
__device__ __forceinline__ __half2 u2h(unsigned u) { return *(__half2*)&u; }

// two fp16 exp2 in one MUFU op
__device__ __forceinline__ unsigned ex2_f16x2(unsigned x) {
    unsigned d;
    asm("ex2.approx.f16x2 %0, %1;" : "=r"(d) : "r"(x));
    return d;
}

// ---------------------------------------------------------------------------
// merged fp32 -> fp16 conversion for x, Wqkv, Wo (one launch)
// ---------------------------------------------------------------------------
#define CN1 (MTOT * DD)
#define CN2 (3 * DD * DD)
#define CN3 (DD * DD)
__global__ void convert_all_kernel(const float* __restrict__ x,
                                   const float* __restrict__ wqkv,
                                   const float* __restrict__ wo,
                                   __half* __restrict__ xh,
                                   __half* __restrict__ wqkvh,
                                   __half* __restrict__ woh)
{
    int i = (blockIdx.x * blockDim.x + threadIdx.x) * 4;
    const float* src;
    __half* dst;
    int off;
    if (i < CN1)             { src = x;    dst = xh;    off = i; }
    else if (i < CN1 + CN2)  { src = wqkv; dst = wqkvh; off = i - CN1; }
    else if (i < CN1 + CN2 + CN3) { src = wo; dst = woh; off = i - CN1 - CN2; }
    else return;
    float4 v = *(const float4*)(src + off);
    *(__half2*)(dst + off)     = __floats2half2_rn(v.x, v.y);
    *(__half2*)(dst + off + 2) = __floats2half2_rn(v.z, v.w);
}

// ---------------------------------------------------------------------------
// FP16 tensor-core GEMM (R14 measured-best): C = A*B + bias.
// Block tile 128x128x32, 128 thr = 4 warps, warp tile 64x64.
// 4-stage cp.async pipeline; exactly one commit per iteration.
// ---------------------------------------------------------------------------
#define TBM 128
#define TBN 128
#define TBK 32
#define ASTR 40
#define BSTR 136
#define ASZH (TBM * ASTR)
#define BSZH (TBK * BSTR)
#define SSZ  (ASZH + BSZH)
#define NSTAGE 4
#define GEMM_SMEM_BYTES (NSTAGE * SSZ * 2)   // 75776

__device__ __forceinline__ void gemm_issue_tile(
    __half* As, const __half* __restrict__ A, const __half* __restrict__ Bm,
    int bm, int bn, int M, int N, int K, int t, int stage, int tid)
{
    __half* Ad = As + stage * SSZ;
    __half* Bd = Ad + ASZH;
    int k0 = t * TBK;
    #pragma unroll
    for (int i = 0; i < 4; i++) {
        int chunk = tid + i * 128;
        int row = chunk >> 2, c8 = (chunk & 3) * 8;
        bool ok = (bm + row) < M;
        cp_async16(Ad + row * ASTR + c8, A + (size_t)(bm + row) * K + k0 + c8, ok);
    }
    #pragma unroll
    for (int i = 0; i < 4; i++) {
        int chunk = tid + i * 128;
        int row = chunk >> 4, c8 = (chunk & 15) * 8;
        cp_async16(Bd + row * BSTR + c8, Bm + (size_t)(k0 + row) * N + bn + c8, true);
    }
    cp_commit();
}

template <bool OUT_HALF>
__global__ __launch_bounds__(128, 2) void gemm_f16_kernel(
    const __half* __restrict__ A, const __half* __restrict__ Bm,
    const float* __restrict__ bias, void* __restrict__ Cout,
    int M, int N, int K)
{
    extern __shared__ __align__(16) char smem_raw[];
    __half* As = (__half*)smem_raw;

    const int tid = threadIdx.x;
    const int lane = tid & 31;
    const int warp = tid >> 5;
    const int wm = (warp & 1) * 64;
    const int wn = (warp >> 1) * 64;
    const int bm = blockIdx.y * TBM;
    const int bn = blockIdx.x * TBN;

    // prefetch bias for this thread's 8 n-tiles (hidden under the k-loop)
    float bpre[8][2];
    #pragma unroll
    for (int nt = 0; nt < 8; nt++) {
        int col = bn + wn + nt * 8 + (lane & 3) * 2;
        bpre[nt][0] = bias[col];
        bpre[nt][1] = bias[col + 1];
    }

    float acc[4][8][4];
    #pragma unroll
    for (int i = 0; i < 4; i++)
        #pragma unroll
        for (int j = 0; j < 8; j++)
            #pragma unroll
            for (int r = 0; r < 4; r++) acc[i][j][r] = 0.f;

    const int nT = K / TBK;

    gemm_issue_tile(As, A, Bm, bm, bn, M, N, K, 0, 0, tid);
    gemm_issue_tile(As, A, Bm, bm, bn, M, N, K, 1, 1, tid);
    gemm_issue_tile(As, A, Bm, bm, bn, M, N, K, 2, 2, tid);

    int stage = 0;
    for (int t = 0; t < nT; t++) {
        cp_wait<2>();        // exactly-one-commit-per-iter => stage t resident
        __syncthreads();

        if (t + 3 < nT)
            gemm_issue_tile(As, A, Bm, bm, bn, M, N, K,
                            t + 3, (stage + 3) % NSTAGE, tid);
        else
            cp_commit();     // empty group keeps the wait<2> invariant exact

        const __half* Ab = As + stage * SSZ;
        const __half* Bb = Ab + ASZH;

        #pragma unroll
        for (int ks = 0; ks < 2; ks++) {
            int k = ks * 16;
            unsigned afr[4][4];
            #pragma unroll
            for (int mt = 0; mt < 4; mt++) {
                const __half* p = Ab + (size_t)(wm + mt * 16 + (lane & 15)) * ASTR
                                  + k + ((lane >> 4) << 3);
                ldsm_x4(afr[mt][0], afr[mt][1], afr[mt][2], afr[mt][3], p);
            }
            #pragma unroll
            for (int np = 0; np < 4; np++) {
                unsigned b0[2], b1[2];
                const __half* p = Bb + (size_t)(k + (lane & 15)) * BSTR
                                  + wn + np * 16 + ((lane >> 4) << 3);
                ldsm_x4_t(b0[0], b0[1], b1[0], b1[1], p);
                #pragma unroll
                for (int mt = 0; mt < 4; mt++) {
                    mma_f16(acc[mt][2 * np],     afr[mt], b0);
                    mma_f16(acc[mt][2 * np + 1], afr[mt], b1);
                }
            }
        }
        stage = (stage + 1) % NSTAGE;
    }

    #pragma unroll
    for (int mt = 0; mt < 4; mt++) {
        int r_lo = bm + wm + mt * 16 + (lane >> 2);
        int r_hi = r_lo + 8;
        #pragma unroll
        for (int nt = 0; nt < 8; nt++) {
            int col = bn + wn + nt * 8 + (lane & 3) * 2;
            float b0 = bpre[nt][0], b1 = bpre[nt][1];
            if (OUT_HALF) {
                __half* C = (__half*)Cout;
                if (r_lo < M)
                    *(__half2*)(C + (size_t)r_lo * N + col) =
                        __floats2half2_rn(acc[mt][nt][0] + b0, acc[mt][nt][1] + b1);
                if (r_hi < M)
                    *(__half2*)(C + (size_t)r_hi * N + col) =
                        __floats2half2_rn(acc[mt][nt][2] + b0, acc[mt][nt][3] + b1);
            } else {
                float* C = (float*)Cout;
                if (r_lo < M)
                    *(float2*)(C + (size_t)r_lo * N + col) =
                        make_float2(acc[mt][nt][0] + b0, acc[mt][nt][1] + b1);
                if (r_hi < M)
                    *(float2*)(C + (size_t)r_hi * N + col) =
                        make_float2(acc[mt][nt][2] + b0, acc[mt][nt][3] + b1);
            }
        }
    }
}

// ---------------------------------------------------------------------------
// FP16 flash attention (causal). 128 thr = 4 warps; Q tile 64 rows.
// log2-space softmax; fp16x2 MUFU exp; row-sum via ones-column in V padding.
// __launch_bounds__(128, 4): cap regs at 128 for 4 CTAs/SM (latency hiding).
// ---------------------------------------------------------------------------
#define QSTR 72
#define AT_TILEH (64 * QSTR)
#define ATTN_SMEM_BYTES (5 * AT_TILEH * 2)   // 46080

__device__ __forceinline__ void attn_issue_kv(
    __half* kdst, __half* vdst, const __half* kptr, const __half* vptr,
    int j, int tid)
{
    #pragma unroll
    for (int i = 0; i < 4; i++) {
        int chunk = tid + i * 128;
        int r = chunk >> 3;
        int c = (chunk & 7) * 8;
        int kv = j * 64 + r;
        if (kv >= LL) kv = LL - 1;   // clamped; masked in S
        cp_async16(kdst + r * QSTR + c, kptr + (size_t)kv * (3 * DD) + c, true);
        cp_async16(vdst + r * QSTR + c, vptr + (size_t)kv * (3 * DD) + c, true);
    }
}

__global__ __launch_bounds__(128, 4) void attn_f16_kernel(
    const __half* __restrict__ qkv, __half* __restrict__ att)
{
    extern __shared__ __align__(16) char smem_raw[];
    __half* qs = (__half*)smem_raw;
    __half* ks = qs + AT_TILEH;
    __half* vs = ks + 2 * AT_TILEH;

    const int tid = threadIdx.x;
    const int lane = tid & 31;
    const int warp = tid >> 5;
    const int qtile = 15 - blockIdx.x;
    const int bh = blockIdx.y;
    const int b = bh >> 4;
    const int h = bh & 15;
    const int q0 = qtile * 64;

    const size_t base = (size_t)b * LL * (3 * DD);
    const __half* qptr = qkv + base + h * HDIM;
    const __half* kptr = qkv + base + DD + h * HDIM;
    const __half* vptr = qkv + base + 2 * DD + h * HDIM;

    attn_issue_kv(ks, vs, kptr, vptr, 0, tid);
    #pragma unroll
    for (int i = 0; i < 4; i++) {
        int chunk = tid + i * 128;
        int r = chunk >> 3;
        int c = (chunk & 7) * 8;
        int qr = q0 + r;
        if (qr >= LL) qr = LL - 1;
        cp_async16(qs + r * QSTR + c, qptr + (size_t)qr * (3 * DD) + c, true);
    }
    cp_commit();

    // Ones in V padding cols 64..71 (both buffers) -> PV extra n-tile = row sums.
    {
        const unsigned ONE2 = 0x3C003C00u;
        uint4 ones4 = make_uint4(ONE2, ONE2, ONE2, ONE2);
        int buf = tid >> 6, row = tid & 63;
        *(uint4*)(vs + buf * AT_TILEH + row * QSTR + 64) = ones4;
    }
    cp_wait<0>();
    __syncthreads();

    // Q fragments, pre-scaled by 0.125 * log2(e)
    const __half2 sc2 = __float2half2_rn(0.125f * 1.4426950408889634f);
    unsigned qa[4][4];
    #pragma unroll
    for (int kc = 0; kc < 4; kc++) {
        const __half* p = qs + (size_t)(warp * 16 + (lane & 15)) * QSTR
                          + kc * 16 + ((lane >> 4) << 3);
        ldsm_x4(qa[kc][0], qa[kc][1], qa[kc][2], qa[kc][3], p);
        #pragma unroll
        for (int i = 0; i < 4; i++)
            qa[kc][i] = h2u(__hmul2(u2h(qa[kc][i]), sc2));
    }

    float o[8][4];
    #pragma unroll
    for (int nt = 0; nt < 8; nt++)
        #pragma unroll
        for (int r = 0; r < 4; r++) o[nt][r] = 0.f;
    float ol[4] = {0.f, 0.f, 0.f, 0.f};
    float m0 = -1e30f, m1 = -1e30f;

    for (int j = 0; j <= qtile; j++) {
        int cur = j & 1;
        int nxt = cur ^ 1;
        if (j > 0) { cp_wait<0>(); __syncthreads(); }

        if (j < qtile) {
            attn_issue_kv(ks + nxt * AT_TILEH, vs + nxt * AT_TILEH,
                          kptr, vptr, j + 1, tid);
            cp_commit();
        }

        const __half* K = ks + cur * AT_TILEH;
        const __half* V = vs + cur * AT_TILEH;

        float s[8][4];
        #pragma unroll
        for (int nt = 0; nt < 8; nt++)
            #pragma unroll
            for (int r = 0; r < 4; r++) s[nt][r] = 0.f;

        #pragma unroll
        for (int kc = 0; kc < 4; kc++) {
            #pragma unroll
            for (int np = 0; np < 4; np++) {
                unsigned b0[2], b1[2];
                const __half* p = K + (size_t)(np * 16 + (lane & 7) + ((lane >> 1) & 8)) * QSTR
                                  + kc * 16 + (lane & 8);
                ldsm_x4(b0[0], b0[1], b1[0], b1[1], p);
                mma_f16(s[2 * np],     qa[kc], b0);
                mma_f16(s[2 * np + 1], qa[kc], b1);
            }
        }

        if (j == qtile) {
            int row_g0 = q0 + warp * 16 + (lane >> 2);
            int row_g1 = row_g0 + 8;
            #pragma unroll
            for (int nt = 0; nt < 8; nt++) {
                int c0 = q0 + nt * 8 + 2 * (lane & 3);
                int c1 = c0 + 1;
                if (c0 > row_g0 || c0 >= LL) s[nt][0] = -1e30f;
                if (c1 > row_g0 || c1 >= LL) s[nt][1] = -1e30f;
                if (c0 > row_g1 || c0 >= LL) s[nt][2] = -1e30f;
                if (c1 > row_g1 || c1 >= LL) s[nt][3] = -1e30f;
            }
        }

        float mx0 = m0, mx1 = m1;
        #pragma unroll
        for (int nt = 0; nt < 8; nt++) {
            mx0 = fmaxf(mx0, fmaxf(s[nt][0], s[nt][1]));
            mx1 = fmaxf(mx1, fmaxf(s[nt][2], s[nt][3]));
        }
        mx0 = fmaxf(mx0, __shfl_xor_sync(0xffffffff, mx0, 1));
        mx0 = fmaxf(mx0, __shfl_xor_sync(0xffffffff, mx0, 2));
        mx1 = fmaxf(mx1, __shfl_xor_sync(0xffffffff, mx1, 1));
        mx1 = fmaxf(mx1, __shfl_xor_sync(0xffffffff, mx1, 2));

        float a0 = exp2f(m0 - mx0);
        float a1 = exp2f(m1 - mx1);
        m0 = mx0; m1 = mx1;

        unsigned pa[4][4];
        #pragma unroll
        for (int kc = 0; kc < 4; kc++) {
            pa[kc][0] = ex2_f16x2(h2u(__floats2half2_rn(s[2 * kc][0] - mx0,
                                                        s[2 * kc][1] - mx0)));
            pa[kc][1] = ex2_f16x2(h2u(__floats2half2_rn(s[2 * kc][2] - mx1,
                                                        s[2 * kc][3] - mx1)));
            pa[kc][2] = ex2_f16x2(h2u(__floats2half2_rn(s[2 * kc + 1][0] - mx0,
                                                        s[2 * kc + 1][1] - mx0)));
            pa[kc][3] = ex2_f16x2(h2u(__floats2half2_rn(s[2 * kc + 1][2] - mx1,
                                                        s[2 * kc + 1][3] - mx1)));
        }

        #pragma unroll
        for (int nt = 0; nt < 8; nt++) {
            o[nt][0] *= a0; o[nt][1] *= a0;
            o[nt][2] *= a1; o[nt][3] *= a1;
        }
        ol[0] *= a0; ol[1] *= a0; ol[2] *= a1; ol[3] *= a1;

        #pragma unroll
        for (int kc = 0; kc < 4; kc++) {
            #pragma unroll
            for (int np = 0; np < 4; np++) {
                unsigned b0[2], b1[2];
                const __half* p = V + (size_t)(kc * 16 + (lane & 15)) * QSTR
                                  + np * 16 + ((lane >> 4) << 3);
                ldsm_x4_t(b0[0], b0[1], b1[0], b1[1], p);
                mma_f16(o[2 * np],     pa[kc], b0);
                mma_f16(o[2 * np + 1], pa[kc], b1);
            }
            unsigned bl[2];
            ldsm_x2_t(bl[0], bl[1],
                      V + (size_t)(kc * 16 + (lane & 15)) * QSTR + 64);
            mma_f16(ol, pa[kc], bl);
        }
    }

    float inv0 = 1.0f / ol[0];
    float inv1 = 1.0f / ol[2];
    int row0 = q0 + warp * 16 + (lane >> 2);
    int row1 = row0 + 8;
    #pragma unroll
    for (int nt = 0; nt < 8; nt++) {
        int col = h * HDIM + nt * 8 + 2 * (lane & 3);
        if (row0 < LL)
            *(__half2*)(att + (size_t)(b * LL + row0) * DD + col) =
                __floats2half2_rn(o[nt][0] * inv0, o[nt][1] * inv0);
        if (row1 < LL)
            *(__half2*)(att + (size_t)(b * LL + row1) * DD + col) =
                __floats2half2_rn(o[nt][2] * inv1, o[nt][3] * inv1);
    }
}

// ---------------------------------------------------------------------------
extern "C" void kernel_launch(void* const* d_in, const int* in_sizes, int n_in,
                              void* d_out, int out_size)
{
    const float* x    = (const float*)d_in[0];
    const float* Wqkv = (const float*)d_in[1];
    const float* bqkv = (const float*)d_in[2];
    const float* Wo   = (const float*)d_in[3];
    const float* bo   = (const float*)d_in[4];
    float* out = (float*)d_out;

    __half *xh, *wqkvh, *woh, *qkvh, *atth;
    cudaGetSymbolAddress((void**)&xh, g_xh);
    cudaGetSymbolAddress((void**)&wqkvh, g_wqkvh);
    cudaGetSymbolAddress((void**)&woh, g_woh);
    cudaGetSymbolAddress((void**)&qkvh, g_qkvh);
    cudaGetSymbolAddress((void**)&atth, g_atth);

    cudaFuncSetAttribute(gemm_f16_kernel<true>,
                         cudaFuncAttributeMaxDynamicSharedMemorySize, GEMM_SMEM_BYTES);
    cudaFuncSetAttribute(gemm_f16_kernel<false>,
                         cudaFuncAttributeMaxDynamicSharedMemorySize, GEMM_SMEM_BYTES);
    cudaFuncSetAttribute(attn_f16_kernel,
                         cudaFuncAttributeMaxDynamicSharedMemorySize, ATTN_SMEM_BYTES);

    // 0) all fp32->fp16 conversions in one launch
    {
        int total4 = (CN1 + CN2 + CN3) / 4;
        convert_all_kernel<<<(total4 + 255) / 256, 256>>>(x, Wqkv, Wo, xh, wqkvh, woh);
    }

    const int gridM = (MTOT + TBM - 1) / TBM;  // 63

    gemm_f16_kernel<true><<<dim3(3 * DD / TBN, gridM), 128, GEMM_SMEM_BYTES>>>(
        xh, wqkvh, bqkv, qkvh, MTOT, 3 * DD, DD);

    attn_f16_kernel<<<dim3(16, BB * HH), 128, ATTN_SMEM_BYTES>>>(qkvh, atth);

    gemm_f16_kernel<false><<<dim3(DD / TBN, gridM), 128, GEMM_SMEM_BYTES>>>(
        atth, woh, bo, out, MTOT, DD, DD);
}